// round 9
// baseline (speedup 1.0000x reference)
#include <cuda_runtime.h>
#include <cstdint>

#define B_  8
#define C_  64
#define CQ_ 8
#define H_  128
#define W_  128
#define HW_ (H_*W_)            // 16384
#define NPIX_ (B_*HW_)         // 131072
#define NELEM_ (B_*C_*HW_)     // 8388608

typedef unsigned long long u64;

// ---- packed fp32x2 helpers (SASS FFMA2 path; exact fp32 per lane) ----
__device__ __forceinline__ u64 fma2(u64 a, u64 b, u64 c) {
    u64 d; asm("fma.rn.f32x2 %0, %1, %2, %3;" : "=l"(d) : "l"(a), "l"(b), "l"(c));
    return d;
}
__device__ __forceinline__ u64 mul2(u64 a, u64 b) {
    u64 d; asm("mul.rn.f32x2 %0, %1, %2;" : "=l"(d) : "l"(a), "l"(b));
    return d;
}
__device__ __forceinline__ u64 add2(u64 a, u64 b) {
    u64 d; asm("add.rn.f32x2 %0, %1, %2;" : "=l"(d) : "l"(a), "l"(b));
    return d;
}
__device__ __forceinline__ u64 pack2(float lo, float hi) {
    u64 d; asm("mov.b64 %0, {%1, %2};" : "=l"(d) : "f"(lo), "f"(hi));
    return d;
}
__device__ __forceinline__ void unpack2(u64 a, float& lo, float& hi) {
    asm("mov.b64 {%0, %1}, %2;" : "=f"(lo), "=f"(hi) : "l"(a));
}

// ---- tf32 helpers ----
__device__ __forceinline__ uint32_t tf32r(float f) {
    uint32_t r; asm("cvt.rna.tf32.f32 %0, %1;" : "=r"(r) : "f"(f));
    return r;
}
__device__ __forceinline__ float tf32f(float f) {
    return __uint_as_float(tf32r(f));
}
__device__ __forceinline__ void mma_tf32(float* d,
    uint32_t a0, uint32_t a1, uint32_t a2, uint32_t a3,
    uint32_t b0, uint32_t b1) {
    asm("mma.sync.aligned.m16n8k8.row.col.f32.tf32.tf32.f32 "
        "{%0,%1,%2,%3}, {%4,%5,%6,%7}, {%8,%9}, {%0,%1,%2,%3};"
        : "+f"(d[0]), "+f"(d[1]), "+f"(d[2]), "+f"(d[3])
        : "r"(a0), "r"(a1), "r"(a2), "r"(a3), "r"(b0), "r"(b1));
}

// ---- scratch (device globals; no allocation allowed) ----
__device__ float g_y[NELEM_];
__device__ float g_y2[NELEM_];
__device__ float g_yT[NELEM_];
__device__ float g_accW[NELEM_];
__device__ float g_accHT[NELEM_];
__device__ float g_lW[NPIX_];
__device__ float g_lHT[NPIX_];

// ---------------- depthwise 3x3 conv, pad 1 ----------------
__global__ void dwconv_kernel(const float* __restrict__ x,
                              const float* __restrict__ wdw,
                              float* __restrict__ y) {
    int idx = blockIdx.x * 256 + threadIdx.x;       // over B*C*H*W
    int w = idx & 127;
    int h = (idx >> 7) & 127;
    int c = (idx >> 14) & 63;
    const float* wp = wdw + c * 9;
    const float* xp = x + (idx & ~16383);           // plane base
    float s = 0.f;
#pragma unroll
    for (int i = 0; i < 3; i++) {
        int hh = h + i - 1;
        if (hh < 0 || hh > 127) continue;
#pragma unroll
        for (int j = 0; j < 3; j++) {
            int ww = w + j - 1;
            if (ww < 0 || ww > 127) continue;
            s += xp[hh * 128 + ww] * wp[i * 3 + j];
        }
    }
    y[idx] = s;
}

// ---------------- packed per-pixel matvec ----------------
__device__ __forceinline__ float dot64p(const float* __restrict__ wrow,
                                        const u64* __restrict__ yp) {
    const ulonglong2* w2 = (const ulonglong2*)wrow;
    u64 s0 = 0ull, s1 = 0ull, s2 = 0ull, s3 = 0ull;
#pragma unroll
    for (int i = 0; i < 8; i++) {
        ulonglong2 a = w2[2 * i], b = w2[2 * i + 1];
        s0 = fma2(yp[4 * i + 0], a.x, s0);
        s1 = fma2(yp[4 * i + 1], a.y, s1);
        s2 = fma2(yp[4 * i + 2], b.x, s2);
        s3 = fma2(yp[4 * i + 3], b.y, s3);
    }
    u64 s = add2(add2(s0, s1), add2(s2, s3));
    float lo, hi; unpack2(s, lo, hi);
    return lo + hi;
}

// ---------------- batched 128x128 plane transpose ----------------
__global__ void transpose_kernel(const float* __restrict__ in, float* __restrict__ out) {
    __shared__ float tile[32][33];
    int p = blockIdx.z;
    const float* ip = in + p * HW_;
    float* op = out + p * HW_;
    int tx = threadIdx.x, ty = threadIdx.y;
    int i0 = blockIdx.y * 32, j0 = blockIdx.x * 32;
#pragma unroll
    for (int r = 0; r < 4; r++)
        tile[ty + 8 * r][tx] = ip[(i0 + ty + 8 * r) * 128 + j0 + tx];
    __syncthreads();
#pragma unroll
    for (int r = 0; r < 4; r++)
        op[(j0 + ty + 8 * r) * 128 + i0 + tx] = tile[tx][ty + 8 * r];
}

// ---------------- fused projection + directional attention ----------------
// Per block: one (b, row) of the (possibly transposed) image.
// Stage 0: load y row [64cin][128t] + weights into smem.
// Stage A: q,k scalar fp32 projection per thread (pixel t = tid); k -> skT.
//          V projection via tf32 mma: svT[t][c] = sum_cin y[cin][t]*wv[c][cin].
// Stage B (phase 1): scalar fp32 logits e=q.k_t, p=exp(e); P -> sP (tf32 bits).
// Stage C (phase 2): Out = P * Vt via tf32 mma; strided store + l.
//
// smem (dynamic): buf[16896] (aliases: yS[64][136]|wvS[64][68]|wqkS[16][64]
//                              during projection; sP[128][132] afterwards)
//                 | svT[128][72] | skT[128][8]
#define ATTN_SMEM_FLOATS (16896 + 128*72 + 128*8)   // 27136 floats = 108544 B
__global__ void __launch_bounds__(128) attn_kernel(
    const float* __restrict__ y, const float* __restrict__ wq,
    const float* __restrict__ wk, const float* __restrict__ wv,
    float* __restrict__ acc_out, float* __restrict__ l_out, int mask_diag) {
    extern __shared__ float smem[];
    float* buf = smem;                               // 16896 floats
    float (*svT)[72] = (float(*)[72])(smem + 16896);
    float (*skT)[8]  = (float(*)[8])(smem + 16896 + 128 * 72);
    float* yS   = buf;                               // [64][136]
    float* wvS  = buf + 64 * 136;                    // [64][68]
    float* wqkS = buf + 64 * 136 + 64 * 68;          // [16][64]
    float (*sP)[132] = (float(*)[132])buf;           // after projection

    int bh = blockIdx.x;
    int b = bh >> 7, r = bh & 127;
    int tid = threadIdx.x;
    int lane = tid & 31, wrp = tid >> 5;
    int gid = lane >> 2, tig = lane & 3;

    // ---- Stage 0: weights + y row ----
    for (int i = tid; i < 512; i += 128) { wqkS[i] = wq[i]; wqkS[512 + i] = wk[i]; }
    for (int i = tid; i < 4096; i += 128) {
        int c = i >> 6, ci = i & 63;
        wvS[c * 68 + ci] = tf32f(wv[i]);             // pre-rounded for mma B
    }
    const float* yb = y + b * C_ * HW_ + r * W_;
#pragma unroll 1
    for (int cin = 0; cin < 64; cin++)
        yS[cin * 136 + tid] = yb[cin * HW_ + tid];
    __syncthreads();

    // ---- Stage A1: scalar q,k projection (fp32) ----
    u64 yp[32];
#pragma unroll
    for (int c2 = 0; c2 < 32; c2++)
        yp[c2] = pack2(yS[(2 * c2) * 136 + tid], yS[(2 * c2 + 1) * 136 + tid]);
    float qv[8];
#pragma unroll 1
    for (int o = 0; o < 8; o++) {
        qv[o] = dot64p(&wqkS[o * 64], yp);
        skT[tid][o] = dot64p(&wqkS[512 + o * 64], yp);   // k
    }
    u64 qp[4];
#pragma unroll
    for (int d = 0; d < 4; d++) qp[d] = pack2(qv[2 * d], qv[2 * d + 1]);

    // ---- Stage A2: V projection via tf32 mma: svT[t][c] ----
    {
        float vacc[2][8][4];
#pragma unroll
        for (int mt = 0; mt < 2; mt++)
#pragma unroll
            for (int nt = 0; nt < 8; nt++)
#pragma unroll
                for (int i = 0; i < 4; i++) vacc[mt][nt][i] = 0.f;

#pragma unroll 1
        for (int kt = 0; kt < 8; kt++) {
            int k0 = kt * 8;
            uint32_t bf0[8], bf1[8];
#pragma unroll
            for (int nt = 0; nt < 8; nt++) {
                bf0[nt] = __float_as_uint(wvS[(nt * 8 + gid) * 68 + k0 + tig]);
                bf1[nt] = __float_as_uint(wvS[(nt * 8 + gid) * 68 + k0 + 4 + tig]);
            }
#pragma unroll
            for (int mt = 0; mt < 2; mt++) {
                int t0 = wrp * 32 + mt * 16;
                // A[m=t][k=cin] = yS[cin][t] (raw fp32 bits -> HW tf32 truncation)
                uint32_t a0 = __float_as_uint(yS[(k0 + tig) * 136 + t0 + gid]);
                uint32_t a1 = __float_as_uint(yS[(k0 + tig) * 136 + t0 + 8 + gid]);
                uint32_t a2 = __float_as_uint(yS[(k0 + 4 + tig) * 136 + t0 + gid]);
                uint32_t a3 = __float_as_uint(yS[(k0 + 4 + tig) * 136 + t0 + 8 + gid]);
#pragma unroll
                for (int nt = 0; nt < 8; nt++)
                    mma_tf32(vacc[mt][nt], a0, a1, a2, a3, bf0[nt], bf1[nt]);
            }
        }
#pragma unroll
        for (int mt = 0; mt < 2; mt++) {
            int t0 = wrp * 32 + mt * 16;
#pragma unroll
            for (int nt = 0; nt < 8; nt++) {
                int cc = nt * 8 + 2 * tig;
                svT[t0 + gid][cc]         = tf32f(vacc[mt][nt][0]);
                svT[t0 + gid][cc + 1]     = tf32f(vacc[mt][nt][1]);
                svT[t0 + 8 + gid][cc]     = tf32f(vacc[mt][nt][2]);
                svT[t0 + 8 + gid][cc + 1] = tf32f(vacc[mt][nt][3]);
            }
        }
    }
    __syncthreads();   // yS/wvS dead; sP may now overwrite buf; skT/svT ready

    // ---- Phase 1: scalar logits (fp32), write P (tf32 bits) ----
    float l = 0.f;
#pragma unroll 1
    for (int t = 0; t < 128; t += 4) {
        float4 pv;
#pragma unroll
        for (int j = 0; j < 4; j++) {
            const ulonglong2* kr = (const ulonglong2*)&skT[t + j][0];
            ulonglong2 k01 = kr[0], k23 = kr[1];
            u64 s = mul2(qp[0], k01.x);
            s = fma2(qp[1], k01.y, s);
            s = fma2(qp[2], k23.x, s);
            s = fma2(qp[3], k23.y, s);
            float lo, hi; unpack2(s, lo, hi);
            float p = __expf(lo + hi);
            if (mask_diag && (t + j) == tid) p = 0.f;   // diag -> weight 0
            l += p;
            ((uint32_t*)&pv)[j] = tf32r(p);
        }
        *(float4*)&sP[tid][t] = pv;
    }
    l_out[b * HW_ + r * W_ + tid] = l;
    __syncthreads();

    // ---- Phase 2: Out = P * Vt via tf32 mma ----
    float acc[2][8][4];
#pragma unroll
    for (int mt = 0; mt < 2; mt++)
#pragma unroll
        for (int n = 0; n < 8; n++)
#pragma unroll
            for (int i = 0; i < 4; i++) acc[mt][n][i] = 0.f;

#pragma unroll 1
    for (int kt = 0; kt < 16; kt++) {
        int k0 = kt * 8;
        uint32_t bf0[8], bf1[8];
#pragma unroll
        for (int n = 0; n < 8; n++) {
            bf0[n] = __float_as_uint(svT[k0 + tig][n * 8 + gid]);
            bf1[n] = __float_as_uint(svT[k0 + tig + 4][n * 8 + gid]);
        }
#pragma unroll
        for (int mt = 0; mt < 2; mt++) {
            int q0 = wrp * 32 + mt * 16;
            uint32_t a0 = __float_as_uint(sP[q0 + gid][k0 + tig]);
            uint32_t a1 = __float_as_uint(sP[q0 + 8 + gid][k0 + tig]);
            uint32_t a2 = __float_as_uint(sP[q0 + gid][k0 + 4 + tig]);
            uint32_t a3 = __float_as_uint(sP[q0 + 8 + gid][k0 + 4 + tig]);
#pragma unroll
            for (int n = 0; n < 8; n++)
                mma_tf32(acc[mt][n], a0, a1, a2, a3, bf0[n], bf1[n]);
        }
    }

    float* ob = acc_out + (b * C_) * HW_ + r * W_;
#pragma unroll
    for (int mt = 0; mt < 2; mt++) {
        int qq = wrp * 32 + mt * 16 + gid;
#pragma unroll
        for (int n = 0; n < 8; n++) {
            int cc = n * 8 + 2 * tig;
            ob[cc * HW_ + qq]           = acc[mt][n][0];
            ob[(cc + 1) * HW_ + qq]     = acc[mt][n][1];
            ob[cc * HW_ + qq + 8]       = acc[mt][n][2];
            ob[(cc + 1) * HW_ + qq + 8] = acc[mt][n][3];
        }
    }
}

// ---------------- combine (fused accHT/lHT transpose) ----------------
__global__ void combine2_kernel(
    const float* __restrict__ yin, const float* __restrict__ accHT,
    const float* __restrict__ accW, const float* __restrict__ lHT,
    const float* __restrict__ lW, const float* __restrict__ gamma,
    float* __restrict__ out) {
    __shared__ float sH[32][33];
    __shared__ float sL[32][33];
    int bc = blockIdx.z;              // b*64 + c
    int b = bc >> 6;
    int h0 = blockIdx.y * 32, w0 = blockIdx.x * 32;
    int tx = threadIdx.x, ty = threadIdx.y;
    const float* aT = accHT + bc * HW_;
    const float* lT = lHT + b * HW_;
#pragma unroll
    for (int r = 0; r < 4; r++) {
        sH[ty + 8 * r][tx] = aT[(w0 + ty + 8 * r) * 128 + h0 + tx];
        sL[ty + 8 * r][tx] = lT[(w0 + ty + 8 * r) * 128 + h0 + tx];
    }
    __syncthreads();
    float g = *gamma;
    const float* yb = yin + bc * HW_;
    const float* wb = accW + bc * HW_;
    const float* lwb = lW + b * HW_;
    float* ob = out + bc * HW_;
#pragma unroll
    for (int r = 0; r < 4; r++) {
        int idx = (h0 + ty + 8 * r) * 128 + w0 + tx;
        float aH = sH[tx][ty + 8 * r];
        float lh = sL[tx][ty + 8 * r];
        ob[idx] = yb[idx] + g * (aH + wb[idx]) / (lh + lwb[idx]);
    }
}

// ---------------- pointwise 1x1 conv ----------------
__global__ void __launch_bounds__(256) pw_kernel(
    const float* __restrict__ in, const float* __restrict__ wpw,
    float* __restrict__ out) {
    __shared__ float ws[4096];
    int tid = threadIdx.x;
    for (int i = tid; i < 4096; i += 256) ws[i] = wpw[i];
    __syncthreads();
    int pix = blockIdx.x * 256 + tid;
    int b = pix >> 14, hw = pix & 16383;
    const float* ip = in + b * C_ * HW_ + hw;
    u64 yp[32];
#pragma unroll
    for (int c = 0; c < 32; c++)
        yp[c] = pack2(ip[(2 * c) * HW_], ip[(2 * c + 1) * HW_]);
#pragma unroll 1
    for (int o = 0; o < 64; o++)
        out[(b * 64 + o) * HW_ + hw] = dot64p(&ws[o * 64], yp);
}

extern "C" void kernel_launch(void* const* d_in, const int* in_sizes, int n_in,
                              void* d_out, int out_size) {
    const float* x    = (const float*)d_in[0];
    const float* w_dw = (const float*)d_in[1];
    const float* wq   = (const float*)d_in[2];
    const float* wk   = (const float*)d_in[3];
    const float* wv   = (const float*)d_in[4];
    const float* gam  = (const float*)d_in[5];
    const float* w_pw = (const float*)d_in[6];
    float* out = (float*)d_out;

    float *y, *y2, *yT, *accW, *accHT, *lW, *lHT;
    cudaGetSymbolAddress((void**)&y, g_y);
    cudaGetSymbolAddress((void**)&y2, g_y2);
    cudaGetSymbolAddress((void**)&yT, g_yT);
    cudaGetSymbolAddress((void**)&accW, g_accW);
    cudaGetSymbolAddress((void**)&accHT, g_accHT);
    cudaGetSymbolAddress((void**)&lW, g_lW);
    cudaGetSymbolAddress((void**)&lHT, g_lHT);

    const int attn_smem = ATTN_SMEM_FLOATS * 4;
    cudaFuncSetAttribute(attn_kernel,
                         cudaFuncAttributeMaxDynamicSharedMemorySize, attn_smem);

    dwconv_kernel<<<NELEM_ / 256, 256>>>(x, w_dw, y);

    const float* cin = y;
    float* cout = y2;
    for (int pass = 0; pass < 2; pass++) {
        // single transpose of the current feature map for the H-direction
        transpose_kernel<<<dim3(4, 4, B_ * C_), dim3(32, 8)>>>(cin, yT);
        // W-direction (rows, no mask) — projects q,k,v in-kernel
        attn_kernel<<<B_ * H_, 128, attn_smem>>>(cin, wq, wk, wv, accW, lW, 0);
        // H-direction (rows of transposed image, diagonal mask)
        attn_kernel<<<B_ * W_, 128, attn_smem>>>(yT, wq, wk, wv, accHT, lHT, 1);
        // combine with fused back-transpose of accHT/lHT
        combine2_kernel<<<dim3(4, 4, B_ * C_), dim3(32, 8)>>>(
            cin, accHT, accW, lHT, lW, gam, cout);
        const float* t = cin; cin = cout; cout = (float*)t;
    }

    pw_kernel<<<NPIX_ / 256, 256>>>(cin, w_pw, out);
}

// round 10
// speedup vs baseline: 1.9470x; 1.9470x over previous
#include <cuda_runtime.h>
#include <cstdint>

#define B_  8
#define C_  64
#define CQ_ 8
#define H_  128
#define W_  128
#define HW_ (H_*W_)            // 16384
#define NPIX_ (B_*HW_)         // 131072
#define NELEM_ (B_*C_*HW_)     // 8388608

typedef unsigned long long u64;

// ---- packed fp32x2 helpers (SASS FFMA2 path; exact fp32 per lane) ----
__device__ __forceinline__ u64 fma2(u64 a, u64 b, u64 c) {
    u64 d; asm("fma.rn.f32x2 %0, %1, %2, %3;" : "=l"(d) : "l"(a), "l"(b), "l"(c));
    return d;
}
__device__ __forceinline__ u64 mul2(u64 a, u64 b) {
    u64 d; asm("mul.rn.f32x2 %0, %1, %2;" : "=l"(d) : "l"(a), "l"(b));
    return d;
}
__device__ __forceinline__ u64 add2(u64 a, u64 b) {
    u64 d; asm("add.rn.f32x2 %0, %1, %2;" : "=l"(d) : "l"(a), "l"(b));
    return d;
}
__device__ __forceinline__ u64 pack2(float lo, float hi) {
    u64 d; asm("mov.b64 %0, {%1, %2};" : "=l"(d) : "f"(lo), "f"(hi));
    return d;
}
__device__ __forceinline__ void unpack2(u64 a, float& lo, float& hi) {
    asm("mov.b64 {%0, %1}, %2;" : "=f"(lo), "=f"(hi) : "l"(a));
}

// ---- tf32 helpers ----
__device__ __forceinline__ uint32_t tf32r(float f) {
    uint32_t r; asm("cvt.rna.tf32.f32 %0, %1;" : "=r"(r) : "f"(f));
    return r;
}
__device__ __forceinline__ float tf32f(float f) {
    return __uint_as_float(tf32r(f));
}
__device__ __forceinline__ void mma_tf32(float* d,
    uint32_t a0, uint32_t a1, uint32_t a2, uint32_t a3,
    uint32_t b0, uint32_t b1) {
    asm("mma.sync.aligned.m16n8k8.row.col.f32.tf32.tf32.f32 "
        "{%0,%1,%2,%3}, {%4,%5,%6,%7}, {%8,%9}, {%0,%1,%2,%3};"
        : "+f"(d[0]), "+f"(d[1]), "+f"(d[2]), "+f"(d[3])
        : "r"(a0), "r"(a1), "r"(a2), "r"(a3), "r"(b0), "r"(b1));
}

// ---- scratch (device globals; no allocation allowed) ----
__device__ float g_y[NELEM_];
__device__ float g_y2[NELEM_];
__device__ float g_yT[NELEM_];
__device__ float g_accW[NELEM_];
__device__ float g_accHT[NELEM_];
__device__ float g_lW[NPIX_];
__device__ float g_lHT[NPIX_];

// ---------------- depthwise 3x3 conv, pad 1 ----------------
__global__ void dwconv_kernel(const float* __restrict__ x,
                              const float* __restrict__ wdw,
                              float* __restrict__ y) {
    int idx = blockIdx.x * 256 + threadIdx.x;       // over B*C*H*W
    int w = idx & 127;
    int h = (idx >> 7) & 127;
    int c = (idx >> 14) & 63;
    const float* wp = wdw + c * 9;
    const float* xp = x + (idx & ~16383);           // plane base
    float s = 0.f;
#pragma unroll
    for (int i = 0; i < 3; i++) {
        int hh = h + i - 1;
        if (hh < 0 || hh > 127) continue;
#pragma unroll
        for (int j = 0; j < 3; j++) {
            int ww = w + j - 1;
            if (ww < 0 || ww > 127) continue;
            s += xp[hh * 128 + ww] * wp[i * 3 + j];
        }
    }
    y[idx] = s;
}

// ---------------- packed per-pixel matvec ----------------
__device__ __forceinline__ float dot64p(const float* __restrict__ wrow,
                                        const u64* __restrict__ yp) {
    const ulonglong2* w2 = (const ulonglong2*)wrow;
    u64 s0 = 0ull, s1 = 0ull, s2 = 0ull, s3 = 0ull;
#pragma unroll
    for (int i = 0; i < 8; i++) {
        ulonglong2 a = w2[2 * i], b = w2[2 * i + 1];
        s0 = fma2(yp[4 * i + 0], a.x, s0);
        s1 = fma2(yp[4 * i + 1], a.y, s1);
        s2 = fma2(yp[4 * i + 2], b.x, s2);
        s3 = fma2(yp[4 * i + 3], b.y, s3);
    }
    u64 s = add2(add2(s0, s1), add2(s2, s3));
    float lo, hi; unpack2(s, lo, hi);
    return lo + hi;
}

// ---------------- batched 128x128 plane transpose ----------------
__global__ void transpose_kernel(const float* __restrict__ in, float* __restrict__ out) {
    __shared__ float tile[32][33];
    int p = blockIdx.z;
    const float* ip = in + p * HW_;
    float* op = out + p * HW_;
    int tx = threadIdx.x, ty = threadIdx.y;
    int i0 = blockIdx.y * 32, j0 = blockIdx.x * 32;
#pragma unroll
    for (int r = 0; r < 4; r++)
        tile[ty + 8 * r][tx] = ip[(i0 + ty + 8 * r) * 128 + j0 + tx];
    __syncthreads();
#pragma unroll
    for (int r = 0; r < 4; r++)
        op[(j0 + ty + 8 * r) * 128 + i0 + tx] = tile[tx][ty + 8 * r];
}

// ---------------- fused projection + directional attention (256 thr) ----------
// Per block: one (b, row). 8 warps.
// smem floats: buf 16896 (yS[64][136]|wvS[64][68]|wqkS[16][64] -> later sP[128][132])
//              | svT[128][72] | sqk[128][16] (k cols 0-7, q cols 8-15) | sl[256]
#define BUF_F   16896
#define SVT_F   (128*72)
#define SQK_F   (128*16)
#define SL_F    256
#define ATTN_SMEM_FLOATS (BUF_F + SVT_F + SQK_F + SL_F)   // 28416 fl = 113664 B
__global__ void __launch_bounds__(256, 2) attn_kernel(
    const float* __restrict__ y, const float* __restrict__ wq,
    const float* __restrict__ wk, const float* __restrict__ wv,
    float* __restrict__ acc_out, float* __restrict__ l_out, int mask_diag) {
    extern __shared__ float smem[];
    float* buf = smem;
    float (*svT)[72] = (float(*)[72])(smem + BUF_F);
    float (*sqk)[16] = (float(*)[16])(smem + BUF_F + SVT_F);
    float* sl        = smem + BUF_F + SVT_F + SQK_F;
    float* yS   = buf;                               // [64][136]
    float* wvS  = buf + 64 * 136;                    // [64][68]
    float* wqkS = buf + 64 * 136 + 64 * 68;          // [16][64]
    float (*sP)[132] = (float(*)[132])buf;           // after projection

    int bh = blockIdx.x;
    int b = bh >> 7, r = bh & 127;
    int tid = threadIdx.x;
    int lane = tid & 31, wrp = tid >> 5;             // 8 warps
    int gid = lane >> 2, tig = lane & 3;
    int pix = tid & 127, which = tid >> 7;           // q(0)/k(1) halves

    // ---- Stage 0: weights + y row (coalesced, high MLP) ----
#pragma unroll
    for (int i = tid; i < 1024; i += 256) wqkS[i] = (i < 512) ? wq[i] : wk[i - 512];
#pragma unroll
    for (int i = tid; i < 4096; i += 256) {
        int c = i >> 6, ci = i & 63;
        wvS[c * 68 + ci] = tf32f(wv[i]);             // pre-rounded for mma B
    }
    const float* yb = y + b * C_ * HW_ + r * W_;
#pragma unroll
    for (int i = tid; i < 8192; i += 256) {
        int cin = i >> 7, t = i & 127;
        yS[cin * 136 + t] = yb[cin * HW_ + t];
    }
    __syncthreads();

    // ---- Stage A1: scalar q,k projection (fp32); thread half picks q or k ----
    {
        u64 yp[32];
#pragma unroll
        for (int c2 = 0; c2 < 32; c2++)
            yp[c2] = pack2(yS[(2 * c2) * 136 + pix], yS[(2 * c2 + 1) * 136 + pix]);
        const float* wbase = &wqkS[which ? 512 : 0];
        int col0 = which ? 0 : 8;                    // k -> cols 0-7, q -> cols 8-15
#pragma unroll 1
        for (int o = 0; o < 8; o++)
            sqk[pix][col0 + o] = dot64p(&wbase[o * 64], yp);
    }

    // ---- Stage A2: V projection via tf32 mma: svT[t][c], warp m-tile t0 ----
    {
        int t0 = wrp * 16;
        float vacc[8][4];
#pragma unroll
        for (int nt = 0; nt < 8; nt++)
#pragma unroll
            for (int i = 0; i < 4; i++) vacc[nt][i] = 0.f;

#pragma unroll 1
        for (int kt = 0; kt < 8; kt++) {
            int k0 = kt * 8;
            uint32_t bf0[8], bf1[8];
#pragma unroll
            for (int nt = 0; nt < 8; nt++) {
                bf0[nt] = __float_as_uint(wvS[(nt * 8 + gid) * 68 + k0 + tig]);
                bf1[nt] = __float_as_uint(wvS[(nt * 8 + gid) * 68 + k0 + 4 + tig]);
            }
            // A[m=t][k=cin] = yS[cin][t] (raw fp32 bits -> HW tf32 truncation)
            uint32_t a0 = __float_as_uint(yS[(k0 + tig) * 136 + t0 + gid]);
            uint32_t a1 = __float_as_uint(yS[(k0 + tig) * 136 + t0 + 8 + gid]);
            uint32_t a2 = __float_as_uint(yS[(k0 + 4 + tig) * 136 + t0 + gid]);
            uint32_t a3 = __float_as_uint(yS[(k0 + 4 + tig) * 136 + t0 + 8 + gid]);
#pragma unroll
            for (int nt = 0; nt < 8; nt++)
                mma_tf32(vacc[nt], a0, a1, a2, a3, bf0[nt], bf1[nt]);
        }
#pragma unroll
        for (int nt = 0; nt < 8; nt++) {
            int cc = nt * 8 + 2 * tig;
            svT[t0 + gid][cc]         = tf32f(vacc[nt][0]);
            svT[t0 + gid][cc + 1]     = tf32f(vacc[nt][1]);
            svT[t0 + 8 + gid][cc]     = tf32f(vacc[nt][2]);
            svT[t0 + 8 + gid][cc + 1] = tf32f(vacc[nt][3]);
        }
    }
    __syncthreads();   // yS/wvS/wqkS dead; sP may overwrite buf; sqk/svT ready

    // ---- Phase 1: scalar logits (fp32); thread half covers 64 keys ----
    {
        u64 qp[4];
        const float* qrow = &sqk[pix][8];
#pragma unroll
        for (int d = 0; d < 4; d++) qp[d] = pack2(qrow[2 * d], qrow[2 * d + 1]);

        float l = 0.f;
        int tbase = which * 64;
#pragma unroll 1
        for (int tt = 0; tt < 64; tt += 4) {
            float4 pv;
#pragma unroll
            for (int j = 0; j < 4; j++) {
                int t = tbase + tt + j;
                const ulonglong2* kr = (const ulonglong2*)&sqk[t][0];
                ulonglong2 k01 = kr[0], k23 = kr[1];
                u64 s = mul2(qp[0], k01.x);
                s = fma2(qp[1], k01.y, s);
                s = fma2(qp[2], k23.x, s);
                s = fma2(qp[3], k23.y, s);
                float lo, hi; unpack2(s, lo, hi);
                float p = __expf(lo + hi);
                if (mask_diag && t == pix) p = 0.f;   // diag -> weight 0
                l += p;
                ((uint32_t*)&pv)[j] = tf32r(p);
            }
            *(float4*)&sP[pix][tbase + tt] = pv;
        }
        sl[tid] = l;
    }
    __syncthreads();
    if (tid < 128)
        l_out[b * HW_ + r * W_ + tid] = sl[tid] + sl[tid + 128];

    // ---- Phase 2: Out = P * Vt via tf32 mma; warp m-tile q0 ----
    int q0 = wrp * 16;
    float acc[8][4];
#pragma unroll
    for (int n = 0; n < 8; n++)
#pragma unroll
        for (int i = 0; i < 4; i++) acc[n][i] = 0.f;

#pragma unroll 1
    for (int kt = 0; kt < 16; kt++) {
        int k0 = kt * 8;
        uint32_t bf0[8], bf1[8];
#pragma unroll
        for (int n = 0; n < 8; n++) {
            bf0[n] = __float_as_uint(svT[k0 + tig][n * 8 + gid]);
            bf1[n] = __float_as_uint(svT[k0 + tig + 4][n * 8 + gid]);
        }
        uint32_t a0 = __float_as_uint(sP[q0 + gid][k0 + tig]);
        uint32_t a1 = __float_as_uint(sP[q0 + 8 + gid][k0 + tig]);
        uint32_t a2 = __float_as_uint(sP[q0 + gid][k0 + 4 + tig]);
        uint32_t a3 = __float_as_uint(sP[q0 + 8 + gid][k0 + 4 + tig]);
#pragma unroll
        for (int n = 0; n < 8; n++)
            mma_tf32(acc[n], a0, a1, a2, a3, bf0[n], bf1[n]);
    }

    float* ob = acc_out + (b * C_) * HW_ + r * W_;
    int qq = q0 + gid;
#pragma unroll
    for (int n = 0; n < 8; n++) {
        int cc = n * 8 + 2 * tig;
        ob[cc * HW_ + qq]           = acc[n][0];
        ob[(cc + 1) * HW_ + qq]     = acc[n][1];
        ob[cc * HW_ + qq + 8]       = acc[n][2];
        ob[(cc + 1) * HW_ + qq + 8] = acc[n][3];
    }
}

// ---------------- combine (fused accHT/lHT transpose) ----------------
__global__ void combine2_kernel(
    const float* __restrict__ yin, const float* __restrict__ accHT,
    const float* __restrict__ accW, const float* __restrict__ lHT,
    const float* __restrict__ lW, const float* __restrict__ gamma,
    float* __restrict__ out) {
    __shared__ float sH[32][33];
    __shared__ float sL[32][33];
    int bc = blockIdx.z;              // b*64 + c
    int b = bc >> 6;
    int h0 = blockIdx.y * 32, w0 = blockIdx.x * 32;
    int tx = threadIdx.x, ty = threadIdx.y;
    const float* aT = accHT + bc * HW_;
    const float* lT = lHT + b * HW_;
#pragma unroll
    for (int r = 0; r < 4; r++) {
        sH[ty + 8 * r][tx] = aT[(w0 + ty + 8 * r) * 128 + h0 + tx];
        sL[ty + 8 * r][tx] = lT[(w0 + ty + 8 * r) * 128 + h0 + tx];
    }
    __syncthreads();
    float g = *gamma;
    const float* yb = yin + bc * HW_;
    const float* wb = accW + bc * HW_;
    const float* lwb = lW + b * HW_;
    float* ob = out + bc * HW_;
#pragma unroll
    for (int r = 0; r < 4; r++) {
        int idx = (h0 + ty + 8 * r) * 128 + w0 + tx;
        float aH = sH[tx][ty + 8 * r];
        float lh = sL[tx][ty + 8 * r];
        ob[idx] = yb[idx] + g * (aH + wb[idx]) / (lh + lwb[idx]);
    }
}

// ---------------- pointwise 1x1 conv ----------------
__global__ void __launch_bounds__(256) pw_kernel(
    const float* __restrict__ in, const float* __restrict__ wpw,
    float* __restrict__ out) {
    __shared__ float ws[4096];
    int tid = threadIdx.x;
    for (int i = tid; i < 4096; i += 256) ws[i] = wpw[i];
    __syncthreads();
    int pix = blockIdx.x * 256 + tid;
    int b = pix >> 14, hw = pix & 16383;
    const float* ip = in + b * C_ * HW_ + hw;
    u64 yp[32];
#pragma unroll
    for (int c = 0; c < 32; c++)
        yp[c] = pack2(ip[(2 * c) * HW_], ip[(2 * c + 1) * HW_]);
#pragma unroll 1
    for (int o = 0; o < 64; o++)
        out[(b * 64 + o) * HW_ + hw] = dot64p(&ws[o * 64], yp);
}

extern "C" void kernel_launch(void* const* d_in, const int* in_sizes, int n_in,
                              void* d_out, int out_size) {
    const float* x    = (const float*)d_in[0];
    const float* w_dw = (const float*)d_in[1];
    const float* wq   = (const float*)d_in[2];
    const float* wk   = (const float*)d_in[3];
    const float* wv   = (const float*)d_in[4];
    const float* gam  = (const float*)d_in[5];
    const float* w_pw = (const float*)d_in[6];
    float* out = (float*)d_out;

    float *y, *y2, *yT, *accW, *accHT, *lW, *lHT;
    cudaGetSymbolAddress((void**)&y, g_y);
    cudaGetSymbolAddress((void**)&y2, g_y2);
    cudaGetSymbolAddress((void**)&yT, g_yT);
    cudaGetSymbolAddress((void**)&accW, g_accW);
    cudaGetSymbolAddress((void**)&accHT, g_accHT);
    cudaGetSymbolAddress((void**)&lW, g_lW);
    cudaGetSymbolAddress((void**)&lHT, g_lHT);

    const int attn_smem = ATTN_SMEM_FLOATS * 4;
    cudaFuncSetAttribute(attn_kernel,
                         cudaFuncAttributeMaxDynamicSharedMemorySize, attn_smem);

    dwconv_kernel<<<NELEM_ / 256, 256>>>(x, w_dw, y);

    const float* cin = y;
    float* cout = y2;
    for (int pass = 0; pass < 2; pass++) {
        // single transpose of the current feature map for the H-direction
        transpose_kernel<<<dim3(4, 4, B_ * C_), dim3(32, 8)>>>(cin, yT);
        // W-direction (rows, no mask) — projects q,k,v in-kernel
        attn_kernel<<<B_ * H_, 256, attn_smem>>>(cin, wq, wk, wv, accW, lW, 0);
        // H-direction (rows of transposed image, diagonal mask)
        attn_kernel<<<B_ * W_, 256, attn_smem>>>(yT, wq, wk, wv, accHT, lHT, 1);
        // combine with fused back-transpose of accHT/lHT
        combine2_kernel<<<dim3(4, 4, B_ * C_), dim3(32, 8)>>>(
            cin, accHT, accW, lHT, lW, gam, cout);
        const float* t = cin; cin = cout; cout = (float*)t;
    }

    pw_kernel<<<NPIX_ / 256, 256>>>(cin, w_pw, out);
}

// round 11
// speedup vs baseline: 2.4186x; 1.2422x over previous
#include <cuda_runtime.h>
#include <cstdint>

#define B_  8
#define C_  64
#define CQ_ 8
#define H_  128
#define W_  128
#define HW_ (H_*W_)            // 16384
#define NPIX_ (B_*HW_)         // 131072
#define NELEM_ (B_*C_*HW_)     // 8388608

typedef unsigned long long u64;

// ---- packed fp32x2 helpers (SASS FFMA2 path; exact fp32 per lane) ----
__device__ __forceinline__ u64 fma2(u64 a, u64 b, u64 c) {
    u64 d; asm("fma.rn.f32x2 %0, %1, %2, %3;" : "=l"(d) : "l"(a), "l"(b), "l"(c));
    return d;
}
__device__ __forceinline__ u64 add2(u64 a, u64 b) {
    u64 d; asm("add.rn.f32x2 %0, %1, %2;" : "=l"(d) : "l"(a), "l"(b));
    return d;
}
__device__ __forceinline__ u64 pack2(float lo, float hi) {
    u64 d; asm("mov.b64 %0, {%1, %2};" : "=l"(d) : "f"(lo), "f"(hi));
    return d;
}
__device__ __forceinline__ void unpack2(u64 a, float& lo, float& hi) {
    asm("mov.b64 {%0, %1}, %2;" : "=f"(lo), "=f"(hi) : "l"(a));
}

// ---- tf32 helpers ----
__device__ __forceinline__ uint32_t tf32r(float f) {
    uint32_t r; asm("cvt.rna.tf32.f32 %0, %1;" : "=r"(r) : "f"(f));
    return r;
}
__device__ __forceinline__ float tf32f(float f) {
    return __uint_as_float(tf32r(f));
}
__device__ __forceinline__ void mma_tf32(float* d,
    uint32_t a0, uint32_t a1, uint32_t a2, uint32_t a3,
    uint32_t b0, uint32_t b1) {
    asm("mma.sync.aligned.m16n8k8.row.col.f32.tf32.tf32.f32 "
        "{%0,%1,%2,%3}, {%4,%5,%6,%7}, {%8,%9}, {%0,%1,%2,%3};"
        : "+f"(d[0]), "+f"(d[1]), "+f"(d[2]), "+f"(d[3])
        : "r"(a0), "r"(a1), "r"(a2), "r"(a3), "r"(b0), "r"(b1));
}

// ---- scratch (device globals; no allocation allowed) ----
__device__ float g_y[NELEM_];
__device__ float g_y2[NELEM_];
__device__ float g_yT[NELEM_];
__device__ float g_accW[NELEM_];
__device__ float g_accHT[NELEM_];
__device__ float g_lW[NPIX_];
__device__ float g_lHT[NPIX_];

// ---------------- depthwise 3x3 conv, pad 1 ----------------
__global__ void dwconv_kernel(const float* __restrict__ x,
                              const float* __restrict__ wdw,
                              float* __restrict__ y) {
    int idx = blockIdx.x * 256 + threadIdx.x;       // over B*C*H*W
    int w = idx & 127;
    int h = (idx >> 7) & 127;
    int c = (idx >> 14) & 63;
    const float* wp = wdw + c * 9;
    const float* xp = x + (idx & ~16383);           // plane base
    float s = 0.f;
#pragma unroll
    for (int i = 0; i < 3; i++) {
        int hh = h + i - 1;
        if (hh < 0 || hh > 127) continue;
#pragma unroll
        for (int j = 0; j < 3; j++) {
            int ww = w + j - 1;
            if (ww < 0 || ww > 127) continue;
            s += xp[hh * 128 + ww] * wp[i * 3 + j];
        }
    }
    y[idx] = s;
}

// ---------------- packed per-pixel matvec (pw kernel) ----------------
__device__ __forceinline__ float dot64p(const float* __restrict__ wrow,
                                        const u64* __restrict__ yp) {
    const ulonglong2* w2 = (const ulonglong2*)wrow;
    u64 s0 = 0ull, s1 = 0ull, s2 = 0ull, s3 = 0ull;
#pragma unroll
    for (int i = 0; i < 8; i++) {
        ulonglong2 a = w2[2 * i], b = w2[2 * i + 1];
        s0 = fma2(yp[4 * i + 0], a.x, s0);
        s1 = fma2(yp[4 * i + 1], a.y, s1);
        s2 = fma2(yp[4 * i + 2], b.x, s2);
        s3 = fma2(yp[4 * i + 3], b.y, s3);
    }
    u64 s = add2(add2(s0, s1), add2(s2, s3));
    float lo, hi; unpack2(s, lo, hi);
    return lo + hi;
}

// ---------------- batched 128x128 plane transpose ----------------
__global__ void transpose_kernel(const float* __restrict__ in, float* __restrict__ out) {
    __shared__ float tile[32][33];
    int p = blockIdx.z;
    const float* ip = in + p * HW_;
    float* op = out + p * HW_;
    int tx = threadIdx.x, ty = threadIdx.y;
    int i0 = blockIdx.y * 32, j0 = blockIdx.x * 32;
#pragma unroll
    for (int r = 0; r < 4; r++)
        tile[ty + 8 * r][tx] = ip[(i0 + ty + 8 * r) * 128 + j0 + tx];
    __syncthreads();
#pragma unroll
    for (int r = 0; r < 4; r++)
        op[(j0 + ty + 8 * r) * 128 + i0 + tx] = tile[tx][ty + 8 * r];
}

// ---------------- fully-mma fused projection + directional attention ------
// Per block: one (b, row); 256 threads, 8 warps, warp m-tile = 16 pixels.
// Proj:  q,k,v = y·W via tf32 mma (A-frags from yS shared across the 3 GEMMs)
// Attn:  per n-tile: E = Q·K^T (mma) -> exp -> quad-shfl permute (C->A frag)
//        -> PV mma accumulate.  P never touches smem.
// smem (floats): region1 = yS[64][136] | wvS[64][68] | wS[16][68]  (14144)
//                (svT[128][72] aliases region1 after projection)
//                sqk[128][20]  (k cols 0-7, q cols 8-15)            (2560)
#define REG1_F 14144
#define SQK_F  (128*20)
#define ATTN_SMEM_FLOATS (REG1_F + SQK_F)   // 16704 fl = 66816 B
__global__ void __launch_bounds__(256, 3) attn_kernel(
    const float* __restrict__ y, const float* __restrict__ wq,
    const float* __restrict__ wk, const float* __restrict__ wv,
    float* __restrict__ acc_out, float* __restrict__ l_out, int mask_diag) {
    extern __shared__ float smem[];
    float* yS  = smem;                       // [64][136]
    float* wvS = smem + 8704;                // [64][68]
    float* wS  = smem + 13056;               // [16][68]: q rows 0-7, k rows 8-15
    float* sqk = smem + REG1_F;              // [128][20]
    float (*svT)[72] = (float(*)[72])smem;   // aliases yS after projection

    int bh = blockIdx.x;
    int b = bh >> 7, r = bh & 127;
    int tid = threadIdx.x;
    int lane = tid & 31, wrp = tid >> 5;
    int gid = lane >> 2, tig = lane & 3;
    int t0 = wrp * 16;

    // ---- Stage 0: weights (tf32-rounded) + y row ----
#pragma unroll
    for (int i = tid; i < 1024; i += 256) {
        float w = (i < 512) ? wq[i] : wk[i - 512];
        int o = i >> 6, ci = i & 63;
        wS[o * 68 + ci] = tf32f(w);
    }
#pragma unroll
    for (int i = tid; i < 4096; i += 256) {
        int c = i >> 6, ci = i & 63;
        wvS[c * 68 + ci] = tf32f(wv[i]);
    }
    const float* yb = y + b * C_ * HW_ + r * W_;
#pragma unroll
    for (int i = tid; i < 8192; i += 256) {
        int cin = i >> 7, t = i & 127;
        yS[cin * 136 + t] = yb[cin * HW_ + t];
    }
    __syncthreads();

    // ---- Projection: q,k,v via tf32 mma (shared A-frags from yS) ----
    float vacc[8][4];
#pragma unroll
    for (int nt = 0; nt < 8; nt++)
#pragma unroll
        for (int i = 0; i < 4; i++) vacc[nt][i] = 0.f;
    float qacc[4] = {0.f, 0.f, 0.f, 0.f};
    float kacc[4] = {0.f, 0.f, 0.f, 0.f};

#pragma unroll 1
    for (int kt = 0; kt < 8; kt++) {
        int k0 = kt * 8;
        // A[m=pix][k=cin] = yS[cin][pix] (raw fp32 bits -> HW tf32 truncation)
        uint32_t a0 = __float_as_uint(yS[(k0 + tig) * 136 + t0 + gid]);
        uint32_t a1 = __float_as_uint(yS[(k0 + tig) * 136 + t0 + 8 + gid]);
        uint32_t a2 = __float_as_uint(yS[(k0 + 4 + tig) * 136 + t0 + gid]);
        uint32_t a3 = __float_as_uint(yS[(k0 + 4 + tig) * 136 + t0 + 8 + gid]);
        // q  (B[k=cin][n=out] = wq[out][cin])
        uint32_t bq0 = __float_as_uint(wS[gid * 68 + k0 + tig]);
        uint32_t bq1 = __float_as_uint(wS[gid * 68 + k0 + 4 + tig]);
        mma_tf32(qacc, a0, a1, a2, a3, bq0, bq1);
        // k
        uint32_t bk0 = __float_as_uint(wS[(8 + gid) * 68 + k0 + tig]);
        uint32_t bk1 = __float_as_uint(wS[(8 + gid) * 68 + k0 + 4 + tig]);
        mma_tf32(kacc, a0, a1, a2, a3, bk0, bk1);
        // v
#pragma unroll
        for (int nt = 0; nt < 8; nt++) {
            uint32_t bf0 = __float_as_uint(wvS[(nt * 8 + gid) * 68 + k0 + tig]);
            uint32_t bf1 = __float_as_uint(wvS[(nt * 8 + gid) * 68 + k0 + 4 + tig]);
            mma_tf32(vacc[nt], a0, a1, a2, a3, bf0, bf1);
        }
    }
    __syncthreads();   // all yS reads complete; svT may overwrite region1

    // ---- Epilogues: q,k -> sqk ; v -> svT ----
    *(float2*)&sqk[(t0 + gid) * 20 + 8 + 2 * tig]     = make_float2(qacc[0], qacc[1]);
    *(float2*)&sqk[(t0 + 8 + gid) * 20 + 8 + 2 * tig] = make_float2(qacc[2], qacc[3]);
    *(float2*)&sqk[(t0 + gid) * 20 + 2 * tig]         = make_float2(kacc[0], kacc[1]);
    *(float2*)&sqk[(t0 + 8 + gid) * 20 + 2 * tig]     = make_float2(kacc[2], kacc[3]);
#pragma unroll
    for (int nt = 0; nt < 8; nt++) {
        int cc = nt * 8 + 2 * tig;
        *(float2*)&svT[t0 + gid][cc]     = make_float2(vacc[nt][0], vacc[nt][1]);
        *(float2*)&svT[t0 + 8 + gid][cc] = make_float2(vacc[nt][2], vacc[nt][3]);
    }
    __syncthreads();

    // ---- Fused QK -> exp -> permute -> PV ----
    uint32_t qa0 = __float_as_uint(sqk[(t0 + gid) * 20 + 8 + tig]);
    uint32_t qa1 = __float_as_uint(sqk[(t0 + 8 + gid) * 20 + 8 + tig]);
    uint32_t qa2 = __float_as_uint(sqk[(t0 + gid) * 20 + 12 + tig]);
    uint32_t qa3 = __float_as_uint(sqk[(t0 + 8 + gid) * 20 + 12 + tig]);

    float acc[8][4];
#pragma unroll
    for (int n = 0; n < 8; n++)
#pragma unroll
        for (int i = 0; i < 4; i++) acc[n][i] = 0.f;
    float lA = 0.f, lB = 0.f;
    int srcA = (lane & ~3) | (tig >> 1);
    int srcB = srcA | 2;
    bool odd = tig & 1;

#pragma unroll 1
    for (int nt = 0; nt < 16; nt++) {
        int n0 = nt * 8;
        // E = Q K^T : B[k=d][n=key] = sqk[key][d]
        uint32_t kb0 = __float_as_uint(sqk[(n0 + gid) * 20 + tig]);
        uint32_t kb1 = __float_as_uint(sqk[(n0 + gid) * 20 + 4 + tig]);
        float e[4] = {0.f, 0.f, 0.f, 0.f};
        mma_tf32(e, qa0, qa1, qa2, qa3, kb0, kb1);
        // exp + diagonal mask (C layout: rows t0+gid / +8, cols n0+2tig / +1)
        float p0 = __expf(e[0]), p1 = __expf(e[1]);
        float p2 = __expf(e[2]), p3 = __expf(e[3]);
        if (mask_diag) {
            int c0 = n0 + 2 * tig;
            int r0 = t0 + gid, r1 = t0 + 8 + gid;
            if (c0 == r0)     p0 = 0.f;
            if (c0 + 1 == r0) p1 = 0.f;
            if (c0 == r1)     p2 = 0.f;
            if (c0 + 1 == r1) p3 = 0.f;
        }
        lA += p0 + p1; lB += p2 + p3;
        // C-frag -> A-frag permute within each quad
        float s0 = __shfl_sync(0xffffffffu, p0, srcA);
        float s1 = __shfl_sync(0xffffffffu, p1, srcA);
        float s2 = __shfl_sync(0xffffffffu, p2, srcA);
        float s3 = __shfl_sync(0xffffffffu, p3, srcA);
        float s4 = __shfl_sync(0xffffffffu, p0, srcB);
        float s5 = __shfl_sync(0xffffffffu, p1, srcB);
        float s6 = __shfl_sync(0xffffffffu, p2, srcB);
        float s7 = __shfl_sync(0xffffffffu, p3, srcB);
        uint32_t a0 = __float_as_uint(odd ? s1 : s0);
        uint32_t a1 = __float_as_uint(odd ? s3 : s2);
        uint32_t a2 = __float_as_uint(odd ? s5 : s4);
        uint32_t a3 = __float_as_uint(odd ? s7 : s6);
        // PV accumulate (same k-block n0)
#pragma unroll
        for (int n = 0; n < 8; n++) {
            uint32_t bf0 = __float_as_uint(svT[n0 + tig][n * 8 + gid]);
            uint32_t bf1 = __float_as_uint(svT[n0 + 4 + tig][n * 8 + gid]);
            mma_tf32(acc[n], a0, a1, a2, a3, bf0, bf1);
        }
    }

    // ---- l reduction (across tig) + stores ----
    lA += __shfl_xor_sync(0xffffffffu, lA, 1);
    lA += __shfl_xor_sync(0xffffffffu, lA, 2);
    lB += __shfl_xor_sync(0xffffffffu, lB, 1);
    lB += __shfl_xor_sync(0xffffffffu, lB, 2);
    if (tig == 0) {
        l_out[b * HW_ + r * W_ + t0 + gid]     = lA;
        l_out[b * HW_ + r * W_ + t0 + 8 + gid] = lB;
    }

    float* ob = acc_out + (b * C_) * HW_ + r * W_;
    int qq = t0 + gid;
#pragma unroll
    for (int n = 0; n < 8; n++) {
        int cc = n * 8 + 2 * tig;
        ob[cc * HW_ + qq]           = acc[n][0];
        ob[(cc + 1) * HW_ + qq]     = acc[n][1];
        ob[cc * HW_ + qq + 8]       = acc[n][2];
        ob[(cc + 1) * HW_ + qq + 8] = acc[n][3];
    }
}

// ---------------- combine (fused accHT/lHT transpose) ----------------
__global__ void combine2_kernel(
    const float* __restrict__ yin, const float* __restrict__ accHT,
    const float* __restrict__ accW, const float* __restrict__ lHT,
    const float* __restrict__ lW, const float* __restrict__ gamma,
    float* __restrict__ out) {
    __shared__ float sH[32][33];
    __shared__ float sL[32][33];
    int bc = blockIdx.z;              // b*64 + c
    int b = bc >> 6;
    int h0 = blockIdx.y * 32, w0 = blockIdx.x * 32;
    int tx = threadIdx.x, ty = threadIdx.y;
    const float* aT = accHT + bc * HW_;
    const float* lT = lHT + b * HW_;
#pragma unroll
    for (int r = 0; r < 4; r++) {
        sH[ty + 8 * r][tx] = aT[(w0 + ty + 8 * r) * 128 + h0 + tx];
        sL[ty + 8 * r][tx] = lT[(w0 + ty + 8 * r) * 128 + h0 + tx];
    }
    __syncthreads();
    float g = *gamma;
    const float* yb = yin + bc * HW_;
    const float* wb = accW + bc * HW_;
    const float* lwb = lW + b * HW_;
    float* ob = out + bc * HW_;
#pragma unroll
    for (int r = 0; r < 4; r++) {
        int idx = (h0 + ty + 8 * r) * 128 + w0 + tx;
        float aH = sH[tx][ty + 8 * r];
        float lh = sL[tx][ty + 8 * r];
        ob[idx] = yb[idx] + g * (aH + wb[idx]) / (lh + lwb[idx]);
    }
}

// ---------------- pointwise 1x1 conv ----------------
__global__ void __launch_bounds__(256) pw_kernel(
    const float* __restrict__ in, const float* __restrict__ wpw,
    float* __restrict__ out) {
    __shared__ float ws[4096];
    int tid = threadIdx.x;
    for (int i = tid; i < 4096; i += 256) ws[i] = wpw[i];
    __syncthreads();
    int pix = blockIdx.x * 256 + tid;
    int b = pix >> 14, hw = pix & 16383;
    const float* ip = in + b * C_ * HW_ + hw;
    u64 yp[32];
#pragma unroll
    for (int c = 0; c < 32; c++)
        yp[c] = pack2(ip[(2 * c) * HW_], ip[(2 * c + 1) * HW_]);
#pragma unroll 1
    for (int o = 0; o < 64; o++)
        out[(b * 64 + o) * HW_ + hw] = dot64p(&ws[o * 64], yp);
}

extern "C" void kernel_launch(void* const* d_in, const int* in_sizes, int n_in,
                              void* d_out, int out_size) {
    const float* x    = (const float*)d_in[0];
    const float* w_dw = (const float*)d_in[1];
    const float* wq   = (const float*)d_in[2];
    const float* wk   = (const float*)d_in[3];
    const float* wv   = (const float*)d_in[4];
    const float* gam  = (const float*)d_in[5];
    const float* w_pw = (const float*)d_in[6];
    float* out = (float*)d_out;

    float *y, *y2, *yT, *accW, *accHT, *lW, *lHT;
    cudaGetSymbolAddress((void**)&y, g_y);
    cudaGetSymbolAddress((void**)&y2, g_y2);
    cudaGetSymbolAddress((void**)&yT, g_yT);
    cudaGetSymbolAddress((void**)&accW, g_accW);
    cudaGetSymbolAddress((void**)&accHT, g_accHT);
    cudaGetSymbolAddress((void**)&lW, g_lW);
    cudaGetSymbolAddress((void**)&lHT, g_lHT);

    const int attn_smem = ATTN_SMEM_FLOATS * 4;
    cudaFuncSetAttribute(attn_kernel,
                         cudaFuncAttributeMaxDynamicSharedMemorySize, attn_smem);

    dwconv_kernel<<<NELEM_ / 256, 256>>>(x, w_dw, y);

    const float* cin = y;
    float* cout = y2;
    for (int pass = 0; pass < 2; pass++) {
        // single transpose of the current feature map for the H-direction
        transpose_kernel<<<dim3(4, 4, B_ * C_), dim3(32, 8)>>>(cin, yT);
        // W-direction (rows, no mask) — fully fused q/k/v + attention
        attn_kernel<<<B_ * H_, 256, attn_smem>>>(cin, wq, wk, wv, accW, lW, 0);
        // H-direction (rows of transposed image, diagonal mask)
        attn_kernel<<<B_ * W_, 256, attn_smem>>>(yT, wq, wk, wv, accHT, lHT, 1);
        // combine with fused back-transpose of accHT/lHT
        combine2_kernel<<<dim3(4, 4, B_ * C_), dim3(32, 8)>>>(
            cin, accHT, accW, lHT, lW, gam, cout);
        const float* t = cin; cin = cout; cout = (float*)t;
    }

    pw_kernel<<<NPIX_ / 256, 256>>>(cin, w_pw, out);
}

// round 12
// speedup vs baseline: 2.4433x; 1.0102x over previous
#include <cuda_runtime.h>
#include <cstdint>

#define B_  8
#define C_  64
#define CQ_ 8
#define H_  128
#define W_  128
#define HW_ (H_*W_)            // 16384
#define NPIX_ (B_*HW_)         // 131072
#define NELEM_ (B_*C_*HW_)     // 8388608

typedef unsigned long long u64;

// ---- packed fp32x2 helpers (SASS FFMA2 path; exact fp32 per lane) ----
__device__ __forceinline__ u64 fma2(u64 a, u64 b, u64 c) {
    u64 d; asm("fma.rn.f32x2 %0, %1, %2, %3;" : "=l"(d) : "l"(a), "l"(b), "l"(c));
    return d;
}
__device__ __forceinline__ u64 add2(u64 a, u64 b) {
    u64 d; asm("add.rn.f32x2 %0, %1, %2;" : "=l"(d) : "l"(a), "l"(b));
    return d;
}
__device__ __forceinline__ u64 pack2(float lo, float hi) {
    u64 d; asm("mov.b64 %0, {%1, %2};" : "=l"(d) : "f"(lo), "f"(hi));
    return d;
}
__device__ __forceinline__ void unpack2(u64 a, float& lo, float& hi) {
    asm("mov.b64 {%0, %1}, %2;" : "=f"(lo), "=f"(hi) : "l"(a));
}

// ---- tf32 helpers ----
__device__ __forceinline__ uint32_t tf32r(float f) {
    uint32_t r; asm("cvt.rna.tf32.f32 %0, %1;" : "=r"(r) : "f"(f));
    return r;
}
__device__ __forceinline__ float tf32f(float f) {
    return __uint_as_float(tf32r(f));
}
__device__ __forceinline__ void mma_tf32(float* d,
    uint32_t a0, uint32_t a1, uint32_t a2, uint32_t a3,
    uint32_t b0, uint32_t b1) {
    asm("mma.sync.aligned.m16n8k8.row.col.f32.tf32.tf32.f32 "
        "{%0,%1,%2,%3}, {%4,%5,%6,%7}, {%8,%9}, {%0,%1,%2,%3};"
        : "+f"(d[0]), "+f"(d[1]), "+f"(d[2]), "+f"(d[3])
        : "r"(a0), "r"(a1), "r"(a2), "r"(a3), "r"(b0), "r"(b1));
}

// ---- scratch (device globals; no allocation allowed) ----
__device__ float g_y[NELEM_];
__device__ float g_y2[NELEM_];
__device__ float g_yT[NELEM_];
__device__ float g_accW[NELEM_];
__device__ float g_accHT[NELEM_];
__device__ float g_lW[NPIX_];
__device__ float g_lHT[NPIX_];

// ---------------- depthwise 3x3 conv, pad 1; emits y AND yT ----------------
__global__ void __launch_bounds__(256) dwconv_kernel(
    const float* __restrict__ x, const float* __restrict__ wdw,
    float* __restrict__ y, float* __restrict__ yT) {
    __shared__ float tile[34][35];
    __shared__ float oT[32][33];
    int p = blockIdx.z;                 // b*C + c
    int c = p & 63;
    int h0 = blockIdx.y * 32, w0 = blockIdx.x * 32;
    int tx = threadIdx.x, ty = threadIdx.y;
    int tid = ty * 32 + tx;
    float wr[9];
#pragma unroll
    for (int i = 0; i < 9; i++) wr[i] = wdw[c * 9 + i];
    const float* xp = x + p * HW_;
#pragma unroll
    for (int idx = tid; idx < 34 * 34; idx += 256) {
        int i = idx / 34, j = idx % 34;
        int hh = h0 - 1 + i, ww = w0 - 1 + j;
        tile[i][j] = (hh >= 0 && hh < 128 && ww >= 0 && ww < 128)
                     ? xp[hh * 128 + ww] : 0.f;
    }
    __syncthreads();
    float* yp = y + p * HW_;
#pragma unroll
    for (int r = 0; r < 4; r++) {
        int i = ty + 8 * r;
        float s = 0.f;
#pragma unroll
        for (int di = 0; di < 3; di++)
#pragma unroll
            for (int dj = 0; dj < 3; dj++)
                s += tile[i + di][tx + dj] * wr[di * 3 + dj];
        yp[(h0 + i) * 128 + w0 + tx] = s;
        oT[i][tx] = s;
    }
    __syncthreads();
    float* ypT = yT + p * HW_;
#pragma unroll
    for (int r = 0; r < 4; r++)
        ypT[(w0 + ty + 8 * r) * 128 + h0 + tx] = oT[tx][ty + 8 * r];
}

// ---------------- packed per-pixel matvec (pw kernel) ----------------
__device__ __forceinline__ float dot64p(const float* __restrict__ wrow,
                                        const u64* __restrict__ yp) {
    const ulonglong2* w2 = (const ulonglong2*)wrow;
    u64 s0 = 0ull, s1 = 0ull, s2 = 0ull, s3 = 0ull;
#pragma unroll
    for (int i = 0; i < 8; i++) {
        ulonglong2 a = w2[2 * i], b = w2[2 * i + 1];
        s0 = fma2(yp[4 * i + 0], a.x, s0);
        s1 = fma2(yp[4 * i + 1], a.y, s1);
        s2 = fma2(yp[4 * i + 2], b.x, s2);
        s3 = fma2(yp[4 * i + 3], b.y, s3);
    }
    u64 s = add2(add2(s0, s1), add2(s2, s3));
    float lo, hi; unpack2(s, lo, hi);
    return lo + hi;
}

// ---------------- fully-mma fused projection + directional attention ------
// (unchanged from R11 — validated at 38.6us/launch)
#define REG1_F 14144
#define SQK_F  (128*20)
#define ATTN_SMEM_FLOATS (REG1_F + SQK_F)   // 16704 fl = 66816 B
__global__ void __launch_bounds__(256, 3) attn_kernel(
    const float* __restrict__ y, const float* __restrict__ wq,
    const float* __restrict__ wk, const float* __restrict__ wv,
    float* __restrict__ acc_out, float* __restrict__ l_out, int mask_diag) {
    extern __shared__ float smem[];
    float* yS  = smem;                       // [64][136]
    float* wvS = smem + 8704;                // [64][68]
    float* wS  = smem + 13056;               // [16][68]: q rows 0-7, k rows 8-15
    float* sqk = smem + REG1_F;              // [128][20]
    float (*svT)[72] = (float(*)[72])smem;   // aliases yS after projection

    int bh = blockIdx.x;
    int b = bh >> 7, r = bh & 127;
    int tid = threadIdx.x;
    int lane = tid & 31, wrp = tid >> 5;
    int gid = lane >> 2, tig = lane & 3;
    int t0 = wrp * 16;

    // ---- Stage 0: weights (tf32-rounded) + y row ----
#pragma unroll
    for (int i = tid; i < 1024; i += 256) {
        float w = (i < 512) ? wq[i] : wk[i - 512];
        int o = i >> 6, ci = i & 63;
        wS[o * 68 + ci] = tf32f(w);
    }
#pragma unroll
    for (int i = tid; i < 4096; i += 256) {
        int c = i >> 6, ci = i & 63;
        wvS[c * 68 + ci] = tf32f(wv[i]);
    }
    const float* yb = y + b * C_ * HW_ + r * W_;
#pragma unroll
    for (int i = tid; i < 8192; i += 256) {
        int cin = i >> 7, t = i & 127;
        yS[cin * 136 + t] = yb[cin * HW_ + t];
    }
    __syncthreads();

    // ---- Projection: q,k,v via tf32 mma (shared A-frags from yS) ----
    float vacc[8][4];
#pragma unroll
    for (int nt = 0; nt < 8; nt++)
#pragma unroll
        for (int i = 0; i < 4; i++) vacc[nt][i] = 0.f;
    float qacc[4] = {0.f, 0.f, 0.f, 0.f};
    float kacc[4] = {0.f, 0.f, 0.f, 0.f};

#pragma unroll 1
    for (int kt = 0; kt < 8; kt++) {
        int k0 = kt * 8;
        uint32_t a0 = __float_as_uint(yS[(k0 + tig) * 136 + t0 + gid]);
        uint32_t a1 = __float_as_uint(yS[(k0 + tig) * 136 + t0 + 8 + gid]);
        uint32_t a2 = __float_as_uint(yS[(k0 + 4 + tig) * 136 + t0 + gid]);
        uint32_t a3 = __float_as_uint(yS[(k0 + 4 + tig) * 136 + t0 + 8 + gid]);
        uint32_t bq0 = __float_as_uint(wS[gid * 68 + k0 + tig]);
        uint32_t bq1 = __float_as_uint(wS[gid * 68 + k0 + 4 + tig]);
        mma_tf32(qacc, a0, a1, a2, a3, bq0, bq1);
        uint32_t bk0 = __float_as_uint(wS[(8 + gid) * 68 + k0 + tig]);
        uint32_t bk1 = __float_as_uint(wS[(8 + gid) * 68 + k0 + 4 + tig]);
        mma_tf32(kacc, a0, a1, a2, a3, bk0, bk1);
#pragma unroll
        for (int nt = 0; nt < 8; nt++) {
            uint32_t bf0 = __float_as_uint(wvS[(nt * 8 + gid) * 68 + k0 + tig]);
            uint32_t bf1 = __float_as_uint(wvS[(nt * 8 + gid) * 68 + k0 + 4 + tig]);
            mma_tf32(vacc[nt], a0, a1, a2, a3, bf0, bf1);
        }
    }
    __syncthreads();   // all yS reads complete; svT may overwrite region1

    // ---- Epilogues: q,k -> sqk ; v -> svT ----
    *(float2*)&sqk[(t0 + gid) * 20 + 8 + 2 * tig]     = make_float2(qacc[0], qacc[1]);
    *(float2*)&sqk[(t0 + 8 + gid) * 20 + 8 + 2 * tig] = make_float2(qacc[2], qacc[3]);
    *(float2*)&sqk[(t0 + gid) * 20 + 2 * tig]         = make_float2(kacc[0], kacc[1]);
    *(float2*)&sqk[(t0 + 8 + gid) * 20 + 2 * tig]     = make_float2(kacc[2], kacc[3]);
#pragma unroll
    for (int nt = 0; nt < 8; nt++) {
        int cc = nt * 8 + 2 * tig;
        *(float2*)&svT[t0 + gid][cc]     = make_float2(vacc[nt][0], vacc[nt][1]);
        *(float2*)&svT[t0 + 8 + gid][cc] = make_float2(vacc[nt][2], vacc[nt][3]);
    }
    __syncthreads();

    // ---- Fused QK -> exp -> permute -> PV ----
    uint32_t qa0 = __float_as_uint(sqk[(t0 + gid) * 20 + 8 + tig]);
    uint32_t qa1 = __float_as_uint(sqk[(t0 + 8 + gid) * 20 + 8 + tig]);
    uint32_t qa2 = __float_as_uint(sqk[(t0 + gid) * 20 + 12 + tig]);
    uint32_t qa3 = __float_as_uint(sqk[(t0 + 8 + gid) * 20 + 12 + tig]);

    float acc[8][4];
#pragma unroll
    for (int n = 0; n < 8; n++)
#pragma unroll
        for (int i = 0; i < 4; i++) acc[n][i] = 0.f;
    float lA = 0.f, lB = 0.f;
    int srcA = (lane & ~3) | (tig >> 1);
    int srcB = srcA | 2;
    bool odd = tig & 1;

#pragma unroll 1
    for (int nt = 0; nt < 16; nt++) {
        int n0 = nt * 8;
        uint32_t kb0 = __float_as_uint(sqk[(n0 + gid) * 20 + tig]);
        uint32_t kb1 = __float_as_uint(sqk[(n0 + gid) * 20 + 4 + tig]);
        float e[4] = {0.f, 0.f, 0.f, 0.f};
        mma_tf32(e, qa0, qa1, qa2, qa3, kb0, kb1);
        float p0 = __expf(e[0]), p1 = __expf(e[1]);
        float p2 = __expf(e[2]), p3 = __expf(e[3]);
        if (mask_diag) {
            int c0 = n0 + 2 * tig;
            int r0 = t0 + gid, r1 = t0 + 8 + gid;
            if (c0 == r0)     p0 = 0.f;
            if (c0 + 1 == r0) p1 = 0.f;
            if (c0 == r1)     p2 = 0.f;
            if (c0 + 1 == r1) p3 = 0.f;
        }
        lA += p0 + p1; lB += p2 + p3;
        float s0 = __shfl_sync(0xffffffffu, p0, srcA);
        float s1 = __shfl_sync(0xffffffffu, p1, srcA);
        float s2 = __shfl_sync(0xffffffffu, p2, srcA);
        float s3 = __shfl_sync(0xffffffffu, p3, srcA);
        float s4 = __shfl_sync(0xffffffffu, p0, srcB);
        float s5 = __shfl_sync(0xffffffffu, p1, srcB);
        float s6 = __shfl_sync(0xffffffffu, p2, srcB);
        float s7 = __shfl_sync(0xffffffffu, p3, srcB);
        uint32_t a0 = __float_as_uint(odd ? s1 : s0);
        uint32_t a1 = __float_as_uint(odd ? s3 : s2);
        uint32_t a2 = __float_as_uint(odd ? s5 : s4);
        uint32_t a3 = __float_as_uint(odd ? s7 : s6);
#pragma unroll
        for (int n = 0; n < 8; n++) {
            uint32_t bf0 = __float_as_uint(svT[n0 + tig][n * 8 + gid]);
            uint32_t bf1 = __float_as_uint(svT[n0 + 4 + tig][n * 8 + gid]);
            mma_tf32(acc[n], a0, a1, a2, a3, bf0, bf1);
        }
    }

    // ---- l reduction (across tig) + stores ----
    lA += __shfl_xor_sync(0xffffffffu, lA, 1);
    lA += __shfl_xor_sync(0xffffffffu, lA, 2);
    lB += __shfl_xor_sync(0xffffffffu, lB, 1);
    lB += __shfl_xor_sync(0xffffffffu, lB, 2);
    if (tig == 0) {
        l_out[b * HW_ + r * W_ + t0 + gid]     = lA;
        l_out[b * HW_ + r * W_ + t0 + 8 + gid] = lB;
    }

    float* ob = acc_out + (b * C_) * HW_ + r * W_;
    int qq = t0 + gid;
#pragma unroll
    for (int n = 0; n < 8; n++) {
        int cc = n * 8 + 2 * tig;
        ob[cc * HW_ + qq]           = acc[n][0];
        ob[(cc + 1) * HW_ + qq]     = acc[n][1];
        ob[cc * HW_ + qq + 8]       = acc[n][2];
        ob[(cc + 1) * HW_ + qq + 8] = acc[n][3];
    }
}

// ---------------- combine (fused accHT/lHT transpose; optional outT) --------
// out[b,c,h,w] = yin + g*(accHT[b,c,w,h] + accW[b,c,h,w]) / (lHT[b,w,h] + lW[b,h,w])
// outT (if non-null): transposed copy of out, for next pass's H-direction.
__global__ void combine2_kernel(
    const float* __restrict__ yin, const float* __restrict__ accHT,
    const float* __restrict__ accW, const float* __restrict__ lHT,
    const float* __restrict__ lW, const float* __restrict__ gamma,
    float* __restrict__ out, float* __restrict__ outT) {
    __shared__ float sH[32][33];
    __shared__ float sL[32][33];
    __shared__ float sO[32][33];
    int bc = blockIdx.z;              // b*64 + c
    int b = bc >> 6;
    int h0 = blockIdx.y * 32, w0 = blockIdx.x * 32;
    int tx = threadIdx.x, ty = threadIdx.y;
    const float* aT = accHT + bc * HW_;
    const float* lT = lHT + b * HW_;
#pragma unroll
    for (int r = 0; r < 4; r++) {
        sH[ty + 8 * r][tx] = aT[(w0 + ty + 8 * r) * 128 + h0 + tx];
        sL[ty + 8 * r][tx] = lT[(w0 + ty + 8 * r) * 128 + h0 + tx];
    }
    __syncthreads();
    float g = *gamma;
    const float* yb = yin + bc * HW_;
    const float* wb = accW + bc * HW_;
    const float* lwb = lW + b * HW_;
    float* ob = out + bc * HW_;
#pragma unroll
    for (int r = 0; r < 4; r++) {
        int i = ty + 8 * r;
        int idx = (h0 + i) * 128 + w0 + tx;
        float aH = sH[tx][i];
        float lh = sL[tx][i];
        float o = yb[idx] + g * (aH + wb[idx]) / (lh + lwb[idx]);
        ob[idx] = o;
        sO[i][tx] = o;
    }
    if (outT) {
        __syncthreads();
        float* obT = outT + bc * HW_;
#pragma unroll
        for (int r = 0; r < 4; r++)
            obT[(w0 + ty + 8 * r) * 128 + h0 + tx] = sO[tx][ty + 8 * r];
    }
}

// ---------------- pointwise 1x1 conv ----------------
__global__ void __launch_bounds__(256) pw_kernel(
    const float* __restrict__ in, const float* __restrict__ wpw,
    float* __restrict__ out) {
    __shared__ float ws[4096];
    int tid = threadIdx.x;
    for (int i = tid; i < 4096; i += 256) ws[i] = wpw[i];
    __syncthreads();
    int pix = blockIdx.x * 256 + tid;
    int b = pix >> 14, hw = pix & 16383;
    const float* ip = in + b * C_ * HW_ + hw;
    u64 yp[32];
#pragma unroll
    for (int c = 0; c < 32; c++)
        yp[c] = pack2(ip[(2 * c) * HW_], ip[(2 * c + 1) * HW_]);
#pragma unroll 1
    for (int o = 0; o < 64; o++)
        out[(b * 64 + o) * HW_ + hw] = dot64p(&ws[o * 64], yp);
}

extern "C" void kernel_launch(void* const* d_in, const int* in_sizes, int n_in,
                              void* d_out, int out_size) {
    const float* x    = (const float*)d_in[0];
    const float* w_dw = (const float*)d_in[1];
    const float* wq   = (const float*)d_in[2];
    const float* wk   = (const float*)d_in[3];
    const float* wv   = (const float*)d_in[4];
    const float* gam  = (const float*)d_in[5];
    const float* w_pw = (const float*)d_in[6];
    float* out = (float*)d_out;

    float *y, *y2, *yT, *accW, *accHT, *lW, *lHT;
    cudaGetSymbolAddress((void**)&y, g_y);
    cudaGetSymbolAddress((void**)&y2, g_y2);
    cudaGetSymbolAddress((void**)&yT, g_yT);
    cudaGetSymbolAddress((void**)&accW, g_accW);
    cudaGetSymbolAddress((void**)&accHT, g_accHT);
    cudaGetSymbolAddress((void**)&lW, g_lW);
    cudaGetSymbolAddress((void**)&lHT, g_lHT);

    const int attn_smem = ATTN_SMEM_FLOATS * 4;
    cudaFuncSetAttribute(attn_kernel,
                         cudaFuncAttributeMaxDynamicSharedMemorySize, attn_smem);

    // dwconv emits y and yT (transposed) in one pass
    dwconv_kernel<<<dim3(4, 4, B_ * C_), dim3(32, 8)>>>(x, w_dw, y, yT);

    // ---- pass 0 ----
    attn_kernel<<<B_ * H_, 256, attn_smem>>>(y,  wq, wk, wv, accW, lW, 0);
    attn_kernel<<<B_ * W_, 256, attn_smem>>>(yT, wq, wk, wv, accHT, lHT, 1);
    combine2_kernel<<<dim3(4, 4, B_ * C_), dim3(32, 8)>>>(
        y, accHT, accW, lHT, lW, gam, y2, yT);   // emits y2 and y2T (in yT buf)

    // ---- pass 1 ----
    attn_kernel<<<B_ * H_, 256, attn_smem>>>(y2, wq, wk, wv, accW, lW, 0);
    attn_kernel<<<B_ * W_, 256, attn_smem>>>(yT, wq, wk, wv, accHT, lHT, 1);
    combine2_kernel<<<dim3(4, 4, B_ * C_), dim3(32, 8)>>>(
        y2, accHT, accW, lHT, lW, gam, y, nullptr);

    pw_kernel<<<NPIX_ / 256, 256>>>(y, w_pw, out);
}

// round 14
// speedup vs baseline: 2.6715x; 1.0934x over previous
#include <cuda_runtime.h>
#include <cstdint>

#define B_  8
#define C_  64
#define CQ_ 8
#define H_  128
#define W_  128
#define HW_ (H_*W_)            // 16384
#define NPIX_ (B_*HW_)         // 131072
#define NELEM_ (B_*C_*HW_)     // 8388608

typedef unsigned long long u64;

// ---- packed fp32x2 helpers (SASS FFMA2 path; exact fp32 per lane) ----
__device__ __forceinline__ u64 fma2(u64 a, u64 b, u64 c) {
    u64 d; asm("fma.rn.f32x2 %0, %1, %2, %3;" : "=l"(d) : "l"(a), "l"(b), "l"(c));
    return d;
}
__device__ __forceinline__ u64 add2(u64 a, u64 b) {
    u64 d; asm("add.rn.f32x2 %0, %1, %2;" : "=l"(d) : "l"(a), "l"(b));
    return d;
}
__device__ __forceinline__ u64 pack2(float lo, float hi) {
    u64 d; asm("mov.b64 %0, {%1, %2};" : "=l"(d) : "f"(lo), "f"(hi));
    return d;
}
__device__ __forceinline__ void unpack2(u64 a, float& lo, float& hi) {
    asm("mov.b64 {%0, %1}, %2;" : "=f"(lo), "=f"(hi) : "l"(a));
}

// ---- tf32 helpers ----
__device__ __forceinline__ uint32_t tf32r(float f) {
    uint32_t r; asm("cvt.rna.tf32.f32 %0, %1;" : "=r"(r) : "f"(f));
    return r;
}
__device__ __forceinline__ float tf32f(float f) {
    return __uint_as_float(tf32r(f));
}
__device__ __forceinline__ void mma_tf32(float* d,
    uint32_t a0, uint32_t a1, uint32_t a2, uint32_t a3,
    uint32_t b0, uint32_t b1) {
    asm("mma.sync.aligned.m16n8k8.row.col.f32.tf32.tf32.f32 "
        "{%0,%1,%2,%3}, {%4,%5,%6,%7}, {%8,%9}, {%0,%1,%2,%3};"
        : "+f"(d[0]), "+f"(d[1]), "+f"(d[2]), "+f"(d[3])
        : "r"(a0), "r"(a1), "r"(a2), "r"(a3), "r"(b0), "r"(b1));
}

// ---- scratch (device globals; no allocation allowed) ----
__device__ float g_y[NELEM_];
__device__ float g_y2[NELEM_];
__device__ float g_yT[NELEM_];
__device__ float g_accW[NELEM_];
__device__ float g_accHT[NELEM_];
__device__ float g_lW[NPIX_];
__device__ float g_lHT[NPIX_];

// ---------------- depthwise 3x3 conv, pad 1; emits y AND yT ----------------
__global__ void __launch_bounds__(256) dwconv_kernel(
    const float* __restrict__ x, const float* __restrict__ wdw,
    float* __restrict__ y, float* __restrict__ yT) {
    __shared__ float tile[34][35];
    __shared__ float oT[32][33];
    int p = blockIdx.z;                 // b*C + c
    int c = p & 63;
    int h0 = blockIdx.y * 32, w0 = blockIdx.x * 32;
    int tx = threadIdx.x, ty = threadIdx.y;
    int tid = ty * 32 + tx;
    float wr[9];
#pragma unroll
    for (int i = 0; i < 9; i++) wr[i] = wdw[c * 9 + i];
    const float* xp = x + p * HW_;
#pragma unroll
    for (int idx = tid; idx < 34 * 34; idx += 256) {
        int i = idx / 34, j = idx % 34;
        int hh = h0 - 1 + i, ww = w0 - 1 + j;
        tile[i][j] = (hh >= 0 && hh < 128 && ww >= 0 && ww < 128)
                     ? xp[hh * 128 + ww] : 0.f;
    }
    __syncthreads();
    float* yp = y + p * HW_;
#pragma unroll
    for (int r = 0; r < 4; r++) {
        int i = ty + 8 * r;
        float s = 0.f;
#pragma unroll
        for (int di = 0; di < 3; di++)
#pragma unroll
            for (int dj = 0; dj < 3; dj++)
                s += tile[i + di][tx + dj] * wr[di * 3 + dj];
        yp[(h0 + i) * 128 + w0 + tx] = s;
        oT[i][tx] = s;
    }
    __syncthreads();
    float* ypT = yT + p * HW_;
#pragma unroll
    for (int r = 0; r < 4; r++)
        ypT[(w0 + ty + 8 * r) * 128 + h0 + tx] = oT[tx][ty + 8 * r];
}

// ---------------- packed per-pixel matvec (pw kernel) ----------------
__device__ __forceinline__ float dot64p(const float* __restrict__ wrow,
                                        const u64* __restrict__ yp) {
    const ulonglong2* w2 = (const ulonglong2*)wrow;
    u64 s0 = 0ull, s1 = 0ull, s2 = 0ull, s3 = 0ull;
#pragma unroll
    for (int i = 0; i < 8; i++) {
        ulonglong2 a = w2[2 * i], b = w2[2 * i + 1];
        s0 = fma2(yp[4 * i + 0], a.x, s0);
        s1 = fma2(yp[4 * i + 1], a.y, s1);
        s2 = fma2(yp[4 * i + 2], b.x, s2);
        s3 = fma2(yp[4 * i + 3], b.y, s3);
    }
    u64 s = add2(add2(s0, s1), add2(s2, s3));
    float lo, hi; unpack2(s, lo, hi);
    return lo + hi;
}

// ---------------- fully-mma fused projection + directional attention ------
// Merged W+H: blockIdx.x < 1024 -> W-direction (inA, no mask);
//             else              -> H-direction (inB, diag mask).
#define REG1_F 14144
#define SQK_F  (128*20)
#define ATTN_SMEM_FLOATS (REG1_F + SQK_F)   // 16704 fl = 66816 B
__global__ void __launch_bounds__(256, 3) attn_kernel(
    const float* __restrict__ inA, const float* __restrict__ inB,
    const float* __restrict__ wq, const float* __restrict__ wk,
    const float* __restrict__ wv,
    float* __restrict__ accA, float* __restrict__ accB,
    float* __restrict__ lA_out, float* __restrict__ lB_out) {
    extern __shared__ float smem[];
    float* yS  = smem;                       // [64][136]
    float* wvS = smem + 8704;                // [64][68]
    float* wS  = smem + 13056;               // [16][68]: q rows 0-7, k rows 8-15
    float* sqk = smem + REG1_F;              // [128][20]
    float (*svT)[72] = (float(*)[72])smem;   // aliases yS after projection

    int half = blockIdx.x >> 10;
    int bh = blockIdx.x & 1023;
    const float* y = half ? inB : inA;
    float* acc_out = half ? accB : accA;
    float* l_out   = half ? lB_out : lA_out;
    int mask_diag  = half;

    int b = bh >> 7, r = bh & 127;
    int tid = threadIdx.x;
    int lane = tid & 31, wrp = tid >> 5;
    int gid = lane >> 2, tig = lane & 3;
    int t0 = wrp * 16;

    // ---- Stage 0: weights (tf32-rounded) + y row ----
#pragma unroll
    for (int i = tid; i < 1024; i += 256) {
        float w = (i < 512) ? wq[i] : wk[i - 512];
        int o = i >> 6, ci = i & 63;
        wS[o * 68 + ci] = tf32f(w);
    }
#pragma unroll
    for (int i = tid; i < 4096; i += 256) {
        int c = i >> 6, ci = i & 63;
        wvS[c * 68 + ci] = tf32f(wv[i]);
    }
    const float* yb = y + b * C_ * HW_ + r * W_;
#pragma unroll
    for (int i = tid; i < 8192; i += 256) {
        int cin = i >> 7, t = i & 127;
        yS[cin * 136 + t] = yb[cin * HW_ + t];
    }
    __syncthreads();

    // ---- Projection: q,k,v via tf32 mma (shared A-frags from yS) ----
    float vacc[8][4];
#pragma unroll
    for (int nt = 0; nt < 8; nt++)
#pragma unroll
        for (int i = 0; i < 4; i++) vacc[nt][i] = 0.f;
    float qacc[4] = {0.f, 0.f, 0.f, 0.f};
    float kacc[4] = {0.f, 0.f, 0.f, 0.f};

#pragma unroll 1
    for (int kt = 0; kt < 8; kt++) {
        int k0 = kt * 8;
        uint32_t a0 = __float_as_uint(yS[(k0 + tig) * 136 + t0 + gid]);
        uint32_t a1 = __float_as_uint(yS[(k0 + tig) * 136 + t0 + 8 + gid]);
        uint32_t a2 = __float_as_uint(yS[(k0 + 4 + tig) * 136 + t0 + gid]);
        uint32_t a3 = __float_as_uint(yS[(k0 + 4 + tig) * 136 + t0 + 8 + gid]);
        uint32_t bq0 = __float_as_uint(wS[gid * 68 + k0 + tig]);
        uint32_t bq1 = __float_as_uint(wS[gid * 68 + k0 + 4 + tig]);
        mma_tf32(qacc, a0, a1, a2, a3, bq0, bq1);
        uint32_t bk0 = __float_as_uint(wS[(8 + gid) * 68 + k0 + tig]);
        uint32_t bk1 = __float_as_uint(wS[(8 + gid) * 68 + k0 + 4 + tig]);
        mma_tf32(kacc, a0, a1, a2, a3, bk0, bk1);
#pragma unroll
        for (int nt = 0; nt < 8; nt++) {
            uint32_t bf0 = __float_as_uint(wvS[(nt * 8 + gid) * 68 + k0 + tig]);
            uint32_t bf1 = __float_as_uint(wvS[(nt * 8 + gid) * 68 + k0 + 4 + tig]);
            mma_tf32(vacc[nt], a0, a1, a2, a3, bf0, bf1);
        }
    }
    __syncthreads();   // all yS reads complete; svT may overwrite region1

    // ---- Epilogues: q,k -> sqk ; v -> svT ----
    *(float2*)&sqk[(t0 + gid) * 20 + 8 + 2 * tig]     = make_float2(qacc[0], qacc[1]);
    *(float2*)&sqk[(t0 + 8 + gid) * 20 + 8 + 2 * tig] = make_float2(qacc[2], qacc[3]);
    *(float2*)&sqk[(t0 + gid) * 20 + 2 * tig]         = make_float2(kacc[0], kacc[1]);
    *(float2*)&sqk[(t0 + 8 + gid) * 20 + 2 * tig]     = make_float2(kacc[2], kacc[3]);
#pragma unroll
    for (int nt = 0; nt < 8; nt++) {
        int cc = nt * 8 + 2 * tig;
        *(float2*)&svT[t0 + gid][cc]     = make_float2(vacc[nt][0], vacc[nt][1]);
        *(float2*)&svT[t0 + 8 + gid][cc] = make_float2(vacc[nt][2], vacc[nt][3]);
    }
    __syncthreads();

    // ---- Fused QK -> exp -> permute -> PV ----
    uint32_t qa0 = __float_as_uint(sqk[(t0 + gid) * 20 + 8 + tig]);
    uint32_t qa1 = __float_as_uint(sqk[(t0 + 8 + gid) * 20 + 8 + tig]);
    uint32_t qa2 = __float_as_uint(sqk[(t0 + gid) * 20 + 12 + tig]);
    uint32_t qa3 = __float_as_uint(sqk[(t0 + 8 + gid) * 20 + 12 + tig]);

    float acc[8][4];
#pragma unroll
    for (int n = 0; n < 8; n++)
#pragma unroll
        for (int i = 0; i < 4; i++) acc[n][i] = 0.f;
    float lA = 0.f, lB = 0.f;
    int srcA = (lane & ~3) | (tig >> 1);
    int srcB = srcA | 2;
    bool odd = tig & 1;

#pragma unroll 1
    for (int nt = 0; nt < 16; nt++) {
        int n0 = nt * 8;
        uint32_t kb0 = __float_as_uint(sqk[(n0 + gid) * 20 + tig]);
        uint32_t kb1 = __float_as_uint(sqk[(n0 + gid) * 20 + 4 + tig]);
        float e[4] = {0.f, 0.f, 0.f, 0.f};
        mma_tf32(e, qa0, qa1, qa2, qa3, kb0, kb1);
        float p0 = __expf(e[0]), p1 = __expf(e[1]);
        float p2 = __expf(e[2]), p3 = __expf(e[3]);
        if (mask_diag) {
            int c0 = n0 + 2 * tig;
            int r0 = t0 + gid, r1 = t0 + 8 + gid;
            if (c0 == r0)     p0 = 0.f;
            if (c0 + 1 == r0) p1 = 0.f;
            if (c0 == r1)     p2 = 0.f;
            if (c0 + 1 == r1) p3 = 0.f;
        }
        lA += p0 + p1; lB += p2 + p3;
        float s0 = __shfl_sync(0xffffffffu, p0, srcA);
        float s1 = __shfl_sync(0xffffffffu, p1, srcA);
        float s2 = __shfl_sync(0xffffffffu, p2, srcA);
        float s3 = __shfl_sync(0xffffffffu, p3, srcA);
        float s4 = __shfl_sync(0xffffffffu, p0, srcB);
        float s5 = __shfl_sync(0xffffffffu, p1, srcB);
        float s6 = __shfl_sync(0xffffffffu, p2, srcB);
        float s7 = __shfl_sync(0xffffffffu, p3, srcB);
        uint32_t a0 = __float_as_uint(odd ? s1 : s0);
        uint32_t a1 = __float_as_uint(odd ? s3 : s2);
        uint32_t a2 = __float_as_uint(odd ? s5 : s4);
        uint32_t a3 = __float_as_uint(odd ? s7 : s6);
#pragma unroll
        for (int n = 0; n < 8; n++) {
            uint32_t bf0 = __float_as_uint(svT[n0 + tig][n * 8 + gid]);
            uint32_t bf1 = __float_as_uint(svT[n0 + 4 + tig][n * 8 + gid]);
            mma_tf32(acc[n], a0, a1, a2, a3, bf0, bf1);
        }
    }

    // ---- l reduction (across tig) + stores ----
    lA += __shfl_xor_sync(0xffffffffu, lA, 1);
    lA += __shfl_xor_sync(0xffffffffu, lA, 2);
    lB += __shfl_xor_sync(0xffffffffu, lB, 1);
    lB += __shfl_xor_sync(0xffffffffu, lB, 2);
    if (tig == 0) {
        l_out[b * HW_ + r * W_ + t0 + gid]     = lA;
        l_out[b * HW_ + r * W_ + t0 + 8 + gid] = lB;
    }

    float* ob = acc_out + (b * C_) * HW_ + r * W_;
    int qq = t0 + gid;
#pragma unroll
    for (int n = 0; n < 8; n++) {
        int cc = n * 8 + 2 * tig;
        ob[cc * HW_ + qq]           = acc[n][0];
        ob[(cc + 1) * HW_ + qq]     = acc[n][1];
        ob[cc * HW_ + qq + 8]       = acc[n][2];
        ob[(cc + 1) * HW_ + qq + 8] = acc[n][3];
    }
}

// ---------------- combine v2 (float4 streams; fused accHT/lHT transpose) ----
// Block: (b,c) plane, 32 h-rows x 128 w.  grid = (4 h-quarters, B*C)
// out = yin + g*(accHT^T + accW)/(lHT^T + lW); optional transposed copy outT.
__global__ void __launch_bounds__(256) combine2_kernel(
    const float* __restrict__ yin, const float* __restrict__ accHT,
    const float* __restrict__ accW, const float* __restrict__ lHT,
    const float* __restrict__ lW, const float* __restrict__ gamma,
    float* __restrict__ out, float* __restrict__ outT) {
    __shared__ float sH[32][132];   // [h_loc][w], row = 528B (16B-aligned)
    __shared__ float sL[32][132];
    int h0 = blockIdx.x * 32;
    int bc = blockIdx.y;            // b*64 + c
    int b = bc >> 6;
    int tid = threadIdx.x;

    // load accHT[w][h0..h0+32) -> sH[h][w]; lHT same -> sL (FULL tile both)
    const float* aT = accHT + bc * HW_;
    const float* lT = lHT + b * HW_;
#pragma unroll
    for (int i = 0; i < 4; i++) {
        int idx = tid + i * 256;            // 1024 float4s each stream
        int w = idx >> 3, hq = idx & 7;
        float4 v = *(const float4*)&aT[w * 128 + h0 + 4 * hq];
        sH[4 * hq + 0][w] = v.x;
        sH[4 * hq + 1][w] = v.y;
        sH[4 * hq + 2][w] = v.z;
        sH[4 * hq + 3][w] = v.w;
        float4 lv = *(const float4*)&lT[w * 128 + h0 + 4 * hq];
        sL[4 * hq + 0][w] = lv.x;
        sL[4 * hq + 1][w] = lv.y;
        sL[4 * hq + 2][w] = lv.z;
        sL[4 * hq + 3][w] = lv.w;
    }
    __syncthreads();

    float g = *gamma;
    const float* yb  = yin + bc * HW_;
    const float* wb  = accW + bc * HW_;
    const float* lwb = lW + b * HW_;
    float* ob = out + bc * HW_;
    int col4 = tid & 31, rowbase = tid >> 5;
#pragma unroll
    for (int j = 0; j < 4; j++) {
        int h_loc = rowbase + 8 * j;
        int base = (h0 + h_loc) * 128 + 4 * col4;
        float4 aH = *(float4*)&sH[h_loc][4 * col4];
        float4 lh = *(float4*)&sL[h_loc][4 * col4];
        float4 yy = *(const float4*)&yb[base];
        float4 aW = *(const float4*)&wb[base];
        float4 lw = *(const float4*)&lwb[base];
        float4 o;
        o.x = yy.x + g * (aH.x + aW.x) / (lh.x + lw.x);
        o.y = yy.y + g * (aH.y + aW.y) / (lh.y + lw.y);
        o.z = yy.z + g * (aH.z + aW.z) / (lh.z + lw.z);
        o.w = yy.w + g * (aH.w + aW.w) / (lh.w + lw.w);
        *(float4*)&ob[base] = o;
        *(float4*)&sH[h_loc][4 * col4] = o;   // own slot: no cross-thread hazard
    }
    if (outT) {
        __syncthreads();
        float* obT = outT + bc * HW_;
#pragma unroll
        for (int i = 0; i < 4; i++) {
            int idx = tid + i * 256;
            int w = idx >> 3, hq = idx & 7;
            float4 ot;
            ot.x = sH[4 * hq + 0][w];
            ot.y = sH[4 * hq + 1][w];
            ot.z = sH[4 * hq + 2][w];
            ot.w = sH[4 * hq + 3][w];
            *(float4*)&obT[w * 128 + h0 + 4 * hq] = ot;
        }
    }
}

// ---------------- pointwise 1x1 conv (validated fp32 FFMA2 version) --------
__global__ void __launch_bounds__(256) pw_kernel(
    const float* __restrict__ in, const float* __restrict__ wpw,
    float* __restrict__ out) {
    __shared__ float ws[4096];
    int tid = threadIdx.x;
    for (int i = tid; i < 4096; i += 256) ws[i] = wpw[i];
    __syncthreads();
    int pix = blockIdx.x * 256 + tid;
    int b = pix >> 14, hw = pix & 16383;
    const float* ip = in + b * C_ * HW_ + hw;
    u64 yp[32];
#pragma unroll
    for (int c = 0; c < 32; c++)
        yp[c] = pack2(ip[(2 * c) * HW_], ip[(2 * c + 1) * HW_]);
#pragma unroll 1
    for (int o = 0; o < 64; o++)
        out[(b * 64 + o) * HW_ + hw] = dot64p(&ws[o * 64], yp);
}

extern "C" void kernel_launch(void* const* d_in, const int* in_sizes, int n_in,
                              void* d_out, int out_size) {
    const float* x    = (const float*)d_in[0];
    const float* w_dw = (const float*)d_in[1];
    const float* wq   = (const float*)d_in[2];
    const float* wk   = (const float*)d_in[3];
    const float* wv   = (const float*)d_in[4];
    const float* gam  = (const float*)d_in[5];
    const float* w_pw = (const float*)d_in[6];
    float* out = (float*)d_out;

    float *y, *y2, *yT, *accW, *accHT, *lW, *lHT;
    cudaGetSymbolAddress((void**)&y, g_y);
    cudaGetSymbolAddress((void**)&y2, g_y2);
    cudaGetSymbolAddress((void**)&yT, g_yT);
    cudaGetSymbolAddress((void**)&accW, g_accW);
    cudaGetSymbolAddress((void**)&accHT, g_accHT);
    cudaGetSymbolAddress((void**)&lW, g_lW);
    cudaGetSymbolAddress((void**)&lHT, g_lHT);

    const int attn_smem = ATTN_SMEM_FLOATS * 4;
    cudaFuncSetAttribute(attn_kernel,
                         cudaFuncAttributeMaxDynamicSharedMemorySize, attn_smem);

    // dwconv emits y and yT (transposed) in one pass
    dwconv_kernel<<<dim3(4, 4, B_ * C_), dim3(32, 8)>>>(x, w_dw, y, yT);

    // ---- pass 0 ----
    attn_kernel<<<2 * B_ * H_, 256, attn_smem>>>(
        y, yT, wq, wk, wv, accW, accHT, lW, lHT);
    combine2_kernel<<<dim3(4, B_ * C_), 256>>>(
        y, accHT, accW, lHT, lW, gam, y2, yT);   // emits y2 and y2T (in yT buf)

    // ---- pass 1 ----
    attn_kernel<<<2 * B_ * H_, 256, attn_smem>>>(
        y2, yT, wq, wk, wv, accW, accHT, lW, lHT);
    combine2_kernel<<<dim3(4, B_ * C_), 256>>>(
        y2, accHT, accW, lHT, lW, gam, y, nullptr);

    pw_kernel<<<NPIX_ / 256, 256>>>(y, w_pw, out);
}